// round 2
// baseline (speedup 1.0000x reference)
#include <cuda_runtime.h>

// Problem constants
#define NB     4
#define SL     2048
#define NHEADS 8
#define HD     64
#define FEA    512
#define NHTOT  32          // NB * NHEADS

#define BQ     128
#define BK     64
#define QPITCH 132         // padded row pitch for Qt / Pt (floats)
#define KPITCH 68          // padded row pitch for Kt (floats)

typedef unsigned long long u64;

// ---------------------------------------------------------------------------
// Scratch (device globals — allocation-free rule)
// ---------------------------------------------------------------------------
__device__ float g_q[NHTOT * SL * HD];     // [nh][l][d]
__device__ float g_k[NHTOT * SL * HD];
__device__ float g_v[NHTOT * SL * HD];
__device__ float g_attn[NB * SL * FEA];    // [n][l][h*64+j]

// ---------------------------------------------------------------------------
// Packed fp32x2 helpers (Blackwell FFMA2 — only reachable via PTX)
// ---------------------------------------------------------------------------
__device__ __forceinline__ u64 fma2(u64 a, u64 b, u64 c) {
    u64 d;
    asm("fma.rn.f32x2 %0, %1, %2, %3;" : "=l"(d) : "l"(a), "l"(b), "l"(c));
    return d;
}
__device__ __forceinline__ u64 pack2(float lo, float hi) {
    u64 r;
    asm("mov.b64 %0, {%1, %2};" : "=l"(r) : "f"(lo), "f"(hi));
    return r;
}
__device__ __forceinline__ float2 unpack2(u64 v) {
    float2 f;
    asm("mov.b64 {%0, %1}, %2;" : "=f"(f.x), "=f"(f.y) : "l"(v));
    return f;
}

// ---------------------------------------------------------------------------
// Kernel 1: per-head projections q/k/v = x_head @ W{q,k,v}   (unchanged, known-good)
// grid (16, 32), block 128 (thread = one l row)
// ---------------------------------------------------------------------------
__global__ void __launch_bounds__(128, 3)
proj_kernel(const float* __restrict__ x,
            const float* __restrict__ Wq,
            const float* __restrict__ Wk,
            const float* __restrict__ Wv)
{
    __shared__ __align__(16) float ws[3][64 * 64];   // 48 KB

    const int nh = blockIdx.y;
    const int n  = nh >> 3;
    const int h  = nh & 7;
    const int l  = blockIdx.x * 128 + threadIdx.x;

    const float* wsrc[3] = {Wq, Wk, Wv};
    #pragma unroll
    for (int m = 0; m < 3; m++)
        for (int i = threadIdx.x; i < 1024; i += 128)
            ((float4*)ws[m])[i] = ((const float4*)wsrc[m])[i];
    __syncthreads();

    float xr[64];
    const float4* xp = (const float4*)(x + ((size_t)n * SL + l) * FEA + h * HD);
    #pragma unroll
    for (int i = 0; i < 16; i++) {
        float4 t = xp[i];
        xr[4*i+0] = t.x; xr[4*i+1] = t.y; xr[4*i+2] = t.z; xr[4*i+3] = t.w;
    }

    const size_t off = ((size_t)nh * SL + l) * HD;
    float* dst[3] = {g_q + off, g_k + off, g_v + off};

    #pragma unroll
    for (int m = 0; m < 3; m++) {
        u64 acc[32];
        #pragma unroll
        for (int i = 0; i < 32; i++) acc[i] = 0ull;

        #pragma unroll 4
        for (int d = 0; d < 64; d++) {
            u64 xd = pack2(xr[d], xr[d]);
            const ulonglong2* wr = (const ulonglong2*)&ws[m][d * 64];
            #pragma unroll
            for (int p = 0; p < 16; p++) {
                ulonglong2 w = wr[p];
                acc[2*p+0] = fma2(xd, w.x, acc[2*p+0]);
                acc[2*p+1] = fma2(xd, w.y, acc[2*p+1]);
            }
        }
        float4* op = (float4*)dst[m];
        #pragma unroll
        for (int i = 0; i < 16; i++) {
            float2 a = unpack2(acc[2*i+0]);
            float2 b = unpack2(acc[2*i+1]);
            op[i] = make_float4(a.x, a.y, b.x, b.y);
        }
    }
}

// ---------------------------------------------------------------------------
// Kernel 2 (REWRITTEN): fused attention  O = relu(Q K^T)^2 V  per (n,h)
// Register-fragment GEMM pair. grid (16, 32) = (q-tile of 128, nh), block 256.
// Thread (qg = tid>>3, kg = tid&7) owns a 4x8 fragment:
//   GEMM1: S[4q x 8k], GEMM2: O[4q x 8d]
// ---------------------------------------------------------------------------
__global__ void __launch_bounds__(256, 2)
attn_kernel()
{
    extern __shared__ __align__(16) float sm[];
    float* Qt = sm;                          // [64][QPITCH]  Q transposed (persistent)
    float* Kt = Qt + 64 * QPITCH;            // [64][KPITCH]  K chunk transposed
    float* Pt = Kt + 64 * KPITCH;            // [64][QPITCH]  relu(S)^2, k-major
    float* Vs = Pt + 64 * QPITCH;            // [64][64]      V chunk, natural

    const int nh  = blockIdx.y;
    const int q0  = blockIdx.x * BQ;
    const int tid = threadIdx.x;
    const int qg  = tid >> 3;                // 0..31
    const int kg  = tid & 7;                 // 0..7
    const int qr  = 4 * qg;                  // owned q rows qr..qr+3
    const int kc  = 8 * kg;                  // owned k (GEMM1) / d (GEMM2) cols

    const float* Qg = g_q + ((size_t)nh * SL + q0) * HD;
    const float* Kg = g_k + (size_t)nh * SL * HD;
    const float* Vg = g_v + (size_t)nh * SL * HD;

    // Stage Qt (transposed): 128 rows x 64 d
    #pragma unroll
    for (int j = 0; j < 8; j++) {
        int idx = tid + j * 256;             // 0..2047
        int r   = idx >> 4;                  // 0..127
        int c4  = (idx & 15) * 4;
        float4 t = *(const float4*)(Qg + (size_t)r * HD + c4);
        Qt[(c4+0) * QPITCH + r] = t.x;
        Qt[(c4+1) * QPITCH + r] = t.y;
        Qt[(c4+2) * QPITCH + r] = t.z;
        Qt[(c4+3) * QPITCH + r] = t.w;
    }

    u64 o2[4][4];
    #pragma unroll
    for (int i = 0; i < 4; i++)
        #pragma unroll
        for (int p = 0; p < 4; p++) o2[i][p] = 0ull;

    for (int cb = 0; cb < SL / BK; cb++) {
        __syncthreads();   // protect Kt/Vs from previous iteration's readers; covers Qt on cb=0

        // Stage Kt (transposed) and Vs (natural): 64x64 each
        const float4* kp = (const float4*)(Kg + (size_t)cb * BK * HD);
        const float4* vp = (const float4*)(Vg + (size_t)cb * BK * HD);
        #pragma unroll
        for (int j = 0; j < 4; j++) {
            int idx = tid + j * 256;         // 0..1023
            int r   = idx >> 4;              // 0..63
            int c4  = (idx & 15) * 4;
            float4 t = kp[idx];
            Kt[(c4+0) * KPITCH + r] = t.x;
            Kt[(c4+1) * KPITCH + r] = t.y;
            Kt[(c4+2) * KPITCH + r] = t.z;
            Kt[(c4+3) * KPITCH + r] = t.w;
            ((float4*)Vs)[idx] = vp[idx];
        }
        __syncthreads();

        // ---- GEMM1: S[4q x 8k] = sum_d Qt[d][q] * Kt[d][k] ----
        u64 s2[4][4];
        #pragma unroll
        for (int i = 0; i < 4; i++)
            #pragma unroll
            for (int p = 0; p < 4; p++) s2[i][p] = 0ull;

        #pragma unroll 8
        for (int d = 0; d < 64; d++) {
            float4 qv = *(const float4*)(Qt + d * QPITCH + qr);
            ulonglong2 k01 = *(const ulonglong2*)(Kt + d * KPITCH + kc);
            ulonglong2 k23 = *(const ulonglong2*)(Kt + d * KPITCH + kc + 4);
            u64 kk0 = k01.x, kk1 = k01.y, kk2 = k23.x, kk3 = k23.y;
            float qa[4] = {qv.x, qv.y, qv.z, qv.w};
            #pragma unroll
            for (int qi = 0; qi < 4; qi++) {
                u64 qq = pack2(qa[qi], qa[qi]);
                s2[qi][0] = fma2(qq, kk0, s2[qi][0]);
                s2[qi][1] = fma2(qq, kk1, s2[qi][1]);
                s2[qi][2] = fma2(qq, kk2, s2[qi][2]);
                s2[qi][3] = fma2(qq, kk3, s2[qi][3]);
            }
        }

        // ---- relu^2, transpose fragment in regs, store k-major Pt[k][q] ----
        float r2[4][8];
        #pragma unroll
        for (int qi = 0; qi < 4; qi++) {
            #pragma unroll
            for (int p = 0; p < 4; p++) {
                float2 f = unpack2(s2[qi][p]);
                float a = fmaxf(f.x, 0.0f);
                float b = fmaxf(f.y, 0.0f);
                r2[qi][2*p+0] = a * a;
                r2[qi][2*p+1] = b * b;
            }
        }
        #pragma unroll
        for (int j = 0; j < 8; j++) {
            float4 v = make_float4(r2[0][j], r2[1][j], r2[2][j], r2[3][j]);
            *(float4*)(Pt + (kc + j) * QPITCH + qr) = v;
        }
        __syncthreads();

        // ---- GEMM2: O[4q x 8d] += sum_k Pt[k][q] * Vs[k][d] ----
        #pragma unroll 8
        for (int k = 0; k < BK; k++) {
            float4 pv = *(const float4*)(Pt + k * QPITCH + qr);
            ulonglong2 v01 = *(const ulonglong2*)(Vs + k * HD + kc);
            ulonglong2 v23 = *(const ulonglong2*)(Vs + k * HD + kc + 4);
            u64 vv0 = v01.x, vv1 = v01.y, vv2 = v23.x, vv3 = v23.y;
            float pa[4] = {pv.x, pv.y, pv.z, pv.w};
            #pragma unroll
            for (int qi = 0; qi < 4; qi++) {
                u64 pq = pack2(pa[qi], pa[qi]);
                o2[qi][0] = fma2(pq, vv0, o2[qi][0]);
                o2[qi][1] = fma2(pq, vv1, o2[qi][1]);
                o2[qi][2] = fma2(pq, vv2, o2[qi][2]);
                o2[qi][3] = fma2(pq, vv3, o2[qi][3]);
            }
        }
    }

    // Epilogue: O rows (q0+qr..+3), d cols kc..kc+7 -> g_attn[n][l][h*64 + d]
    const int n = nh >> 3, h = nh & 7;
    #pragma unroll
    for (int qi = 0; qi < 4; qi++) {
        float2 a = unpack2(o2[qi][0]);
        float2 b = unpack2(o2[qi][1]);
        float2 c = unpack2(o2[qi][2]);
        float2 d = unpack2(o2[qi][3]);
        float* op = g_attn + ((size_t)n * SL + q0 + qr + qi) * FEA + h * HD + kc;
        *(float4*)(op)     = make_float4(a.x, a.y, b.x, b.y);
        *(float4*)(op + 4) = make_float4(c.x, c.y, d.x, d.y);
    }
}

// ---------------------------------------------------------------------------
// Kernel 3: out = g_attn[8192,512] @ Wo[512,64] + bo   (unchanged)
// ---------------------------------------------------------------------------
__global__ void __launch_bounds__(256)
out_kernel(const float* __restrict__ Wo,
           const float* __restrict__ bo,
           float* __restrict__ out)
{
    __shared__ __align__(16) float xs[64][68];
    __shared__ __align__(16) float wsh[64][64];

    const int row0 = blockIdx.x * 64;
    const int tid  = threadIdx.x;
    const int ty   = tid >> 4, tx = tid & 15;
    const int r0   = ty * 4,  c0 = tx * 4;

    u64 acc[4][2];
    #pragma unroll
    for (int i = 0; i < 4; i++) { acc[i][0] = 0ull; acc[i][1] = 0ull; }

    for (int kcb = 0; kcb < FEA; kcb += 64) {
        __syncthreads();
        #pragma unroll
        for (int j = 0; j < 4; j++) {
            int f  = tid + j * 256;
            int r  = f >> 4;
            int k4 = (f & 15) * 4;
            float4 xv = *(const float4*)(g_attn + ((size_t)(row0 + r)) * FEA + kcb + k4);
            *(float4*)&xs[r][k4] = xv;
            float4 wv = *(const float4*)(Wo + (size_t)(kcb + r) * HD + k4);
            *(float4*)&wsh[r][k4] = wv;
        }
        __syncthreads();

        #pragma unroll 8
        for (int k = 0; k < 64; k++) {
            ulonglong2 wv = *(const ulonglong2*)&wsh[k][c0];
            #pragma unroll
            for (int i = 0; i < 4; i++) {
                float xv = xs[r0 + i][k];
                u64 x2 = pack2(xv, xv);
                acc[i][0] = fma2(x2, wv.x, acc[i][0]);
                acc[i][1] = fma2(x2, wv.y, acc[i][1]);
            }
        }
    }

    float4 bv = *(const float4*)(bo + c0);
    #pragma unroll
    for (int i = 0; i < 4; i++) {
        float2 a = unpack2(acc[i][0]);
        float2 b = unpack2(acc[i][1]);
        float4 o = make_float4(a.x + bv.x, a.y + bv.y, b.x + bv.z, b.y + bv.w);
        *(float4*)(out + (size_t)(row0 + r0 + i) * HD + c0) = o;
    }
}

// ---------------------------------------------------------------------------
// Entry point
// ---------------------------------------------------------------------------
extern "C" void kernel_launch(void* const* d_in, const int* in_sizes, int n_in,
                              void* d_out, int out_size)
{
    const float* query = (const float*)d_in[0];
    const float* Wv    = (const float*)d_in[1];
    const float* Wk    = (const float*)d_in[2];
    const float* Wq    = (const float*)d_in[3];
    const float* Wo    = (const float*)d_in[4];
    const float* bo    = (const float*)d_in[5];
    float* out = (float*)d_out;

    const int attn_smem = (64 * QPITCH + 64 * KPITCH + 64 * QPITCH + 64 * HD) * 4;
    cudaFuncSetAttribute(attn_kernel, cudaFuncAttributeMaxDynamicSharedMemorySize, attn_smem);

    proj_kernel<<<dim3(16, 32), 128>>>(query, Wq, Wk, Wv);
    attn_kernel<<<dim3(16, 32), 256, attn_smem>>>();
    out_kernel<<<128, 256>>>(Wo, bo, out);
}

// round 3
// speedup vs baseline: 1.0080x; 1.0080x over previous
#include <cuda_runtime.h>

// Problem constants
#define NB     4
#define SL     2048
#define HD     64
#define FEA    512
#define NHTOT  32          // NB * NHEADS

#define BQ     128
#define BK     64
#define QP     132         // padded pitch for Qt / Pt (floats)
#define KP     68          // padded pitch for Kt (floats)
#define XP     132         // padded pitch for Xt in proj (floats)

typedef unsigned long long u64;

// ---------------------------------------------------------------------------
// Scratch (device globals — allocation-free rule)
// ---------------------------------------------------------------------------
__device__ float g_q[NHTOT * SL * HD];
__device__ float g_k[NHTOT * SL * HD];
__device__ float g_v[NHTOT * SL * HD];
__device__ float g_attn[NB * SL * FEA];

// ---------------------------------------------------------------------------
// Packed fp32x2 helpers (Blackwell FFMA2)
// ---------------------------------------------------------------------------
__device__ __forceinline__ u64 fma2(u64 a, u64 b, u64 c) {
    u64 d;
    asm("fma.rn.f32x2 %0, %1, %2, %3;" : "=l"(d) : "l"(a), "l"(b), "l"(c));
    return d;
}
__device__ __forceinline__ u64 pack2(float lo, float hi) {
    u64 r;
    asm("mov.b64 %0, {%1, %2};" : "=l"(r) : "f"(lo), "f"(hi));
    return r;
}
__device__ __forceinline__ float2 unpack2(u64 v) {
    float2 f;
    asm("mov.b64 {%0, %1}, %2;" : "=f"(f.x), "=f"(f.y) : "l"(v));
    return f;
}

// ---------------------------------------------------------------------------
// Kernel 1 (REWRITTEN): projections via fragment GEMM.
// grid (16, 32) = (l-tile of 128, nh), block 256.
// Thread (qg=tid>>3, kg=tid&7) owns a 4l x 8e fragment per matrix m.
// ---------------------------------------------------------------------------
__global__ void __launch_bounds__(256, 2)
proj_kernel(const float* __restrict__ x,
            const float* __restrict__ Wq,
            const float* __restrict__ Wk,
            const float* __restrict__ Wv)
{
    extern __shared__ __align__(16) float sm[];
    float* Xt = sm;                 // [64][XP]  x-head slice, transposed
    float* Ws = Xt + 64 * XP;       // [3][64*64] natural

    const int nh = blockIdx.y;
    const int n  = nh >> 3;
    const int h  = nh & 7;
    const int l0 = blockIdx.x * BQ;
    const int tid = threadIdx.x;
    const int qr = (tid >> 3) * 4;  // owned l rows (0..124)
    const int kc = (tid & 7) * 8;   // owned e cols (0..56)

    // Stage weights (natural layout)
    const float* wsrc[3] = {Wq, Wk, Wv};
    #pragma unroll
    for (int m = 0; m < 3; m++)
        #pragma unroll
        for (int i = 0; i < 4; i++)
            ((float4*)(Ws + m * 4096))[tid + i * 256] =
                ((const float4*)wsrc[m])[tid + i * 256];

    // Stage Xt (transposed): 128 rows x 64 d
    #pragma unroll
    for (int j = 0; j < 8; j++) {
        int idx = tid + j * 256;                 // 0..2047
        int r   = idx >> 4;                      // 0..127
        int c4  = (idx & 15) * 4;
        float4 t = *(const float4*)(x + ((size_t)n * SL + l0 + r) * FEA + h * HD + c4);
        Xt[(c4+0) * XP + r] = t.x;
        Xt[(c4+1) * XP + r] = t.y;
        Xt[(c4+2) * XP + r] = t.z;
        Xt[(c4+3) * XP + r] = t.w;
    }
    __syncthreads();

    float* dsts[3] = {g_q, g_k, g_v};

    #pragma unroll
    for (int m = 0; m < 3; m++) {
        u64 s2[4][4];
        #pragma unroll
        for (int qi = 0; qi < 4; qi++)
            #pragma unroll
            for (int p = 0; p < 4; p++) s2[qi][p] = 0ull;

        const float* wb = Ws + m * 4096 + kc;
        #pragma unroll 8
        for (int d = 0; d < 64; d++) {
            float4 qv = *(const float4*)(Xt + d * XP + qr);
            u64 q0 = pack2(qv.x, qv.x), q1 = pack2(qv.y, qv.y);
            u64 q2 = pack2(qv.z, qv.z), q3 = pack2(qv.w, qv.w);
            ulonglong2 w01 = *(const ulonglong2*)(wb + d * 64);
            ulonglong2 w23 = *(const ulonglong2*)(wb + d * 64 + 4);
            s2[0][0] = fma2(q0, w01.x, s2[0][0]); s2[0][1] = fma2(q0, w01.y, s2[0][1]);
            s2[0][2] = fma2(q0, w23.x, s2[0][2]); s2[0][3] = fma2(q0, w23.y, s2[0][3]);
            s2[1][0] = fma2(q1, w01.x, s2[1][0]); s2[1][1] = fma2(q1, w01.y, s2[1][1]);
            s2[1][2] = fma2(q1, w23.x, s2[1][2]); s2[1][3] = fma2(q1, w23.y, s2[1][3]);
            s2[2][0] = fma2(q2, w01.x, s2[2][0]); s2[2][1] = fma2(q2, w01.y, s2[2][1]);
            s2[2][2] = fma2(q2, w23.x, s2[2][2]); s2[2][3] = fma2(q2, w23.y, s2[2][3]);
            s2[3][0] = fma2(q3, w01.x, s2[3][0]); s2[3][1] = fma2(q3, w01.y, s2[3][1]);
            s2[3][2] = fma2(q3, w23.x, s2[3][2]); s2[3][3] = fma2(q3, w23.y, s2[3][3]);
        }

        float* dst = dsts[m] + ((size_t)nh * SL + l0 + qr) * HD + kc;
        #pragma unroll
        for (int qi = 0; qi < 4; qi++) {
            float2 a = unpack2(s2[qi][0]);
            float2 b = unpack2(s2[qi][1]);
            float2 c = unpack2(s2[qi][2]);
            float2 d = unpack2(s2[qi][3]);
            *(float4*)(dst + (size_t)qi * HD)     = make_float4(a.x, a.y, b.x, b.y);
            *(float4*)(dst + (size_t)qi * HD + 4) = make_float4(c.x, c.y, d.x, d.y);
        }
    }
}

// ---------------------------------------------------------------------------
// Kernel 2: fused attention, fragment GEMM pair, register-frugal.
// grid (16, 32), block 256. Thread owns S[4q x 8k] then O[4q x 8d].
// ---------------------------------------------------------------------------
__global__ void __launch_bounds__(256, 2)
attn_kernel()
{
    extern __shared__ __align__(16) float sm[];
    float* Qt = sm;                 // [64][QP] Q transposed (persistent)
    float* Kt = Qt + 64 * QP;       // [64][KP] K chunk transposed
    float* Pt = Kt + 64 * KP;       // [64][QP] relu(S)^2, k-major
    float* Vs = Pt + 64 * QP;       // [64][64] V chunk natural

    const int nh  = blockIdx.y;
    const int q0  = blockIdx.x * BQ;
    const int tid = threadIdx.x;
    const int qr  = (tid >> 3) * 4;
    const int kc  = (tid & 7) * 8;

    const float* Qg = g_q + ((size_t)nh * SL + q0) * HD;
    const float* Kg = g_k + (size_t)nh * SL * HD;
    const float* Vg = g_v + (size_t)nh * SL * HD;

    // Stage Qt (transposed): 128 x 64
    #pragma unroll
    for (int j = 0; j < 8; j++) {
        int idx = tid + j * 256;
        int r   = idx >> 4;
        int c4  = (idx & 15) * 4;
        float4 t = *(const float4*)(Qg + (size_t)r * HD + c4);
        Qt[(c4+0) * QP + r] = t.x;
        Qt[(c4+1) * QP + r] = t.y;
        Qt[(c4+2) * QP + r] = t.z;
        Qt[(c4+3) * QP + r] = t.w;
    }

    u64 o2[4][4];
    #pragma unroll
    for (int qi = 0; qi < 4; qi++)
        #pragma unroll
        for (int p = 0; p < 4; p++) o2[qi][p] = 0ull;

    for (int cb = 0; cb < SL / BK; cb++) {
        __syncthreads();   // protects Kt/Vs rewrite; covers Qt staging on cb=0

        const float4* kp = (const float4*)(Kg + (size_t)cb * BK * HD);
        const float4* vp = (const float4*)(Vg + (size_t)cb * BK * HD);
        #pragma unroll
        for (int j = 0; j < 4; j++) {
            int idx = tid + j * 256;
            int r   = idx >> 4;
            int c4  = (idx & 15) * 4;
            float4 t = kp[idx];
            Kt[(c4+0) * KP + r] = t.x;
            Kt[(c4+1) * KP + r] = t.y;
            Kt[(c4+2) * KP + r] = t.z;
            Kt[(c4+3) * KP + r] = t.w;
            ((float4*)Vs)[idx] = vp[idx];
        }
        __syncthreads();

        // ---- GEMM1: S[4q x 8k] = sum_d Qt[d][q] * Kt[d][k] ----
        u64 s2[4][4];
        #pragma unroll
        for (int qi = 0; qi < 4; qi++)
            #pragma unroll
            for (int p = 0; p < 4; p++) s2[qi][p] = 0ull;

        #pragma unroll 8
        for (int d = 0; d < 64; d++) {
            float4 qv = *(const float4*)(Qt + d * QP + qr);
            u64 q0r = pack2(qv.x, qv.x), q1r = pack2(qv.y, qv.y);
            u64 q2r = pack2(qv.z, qv.z), q3r = pack2(qv.w, qv.w);
            ulonglong2 k01 = *(const ulonglong2*)(Kt + d * KP + kc);
            ulonglong2 k23 = *(const ulonglong2*)(Kt + d * KP + kc + 4);
            s2[0][0] = fma2(q0r, k01.x, s2[0][0]); s2[0][1] = fma2(q0r, k01.y, s2[0][1]);
            s2[0][2] = fma2(q0r, k23.x, s2[0][2]); s2[0][3] = fma2(q0r, k23.y, s2[0][3]);
            s2[1][0] = fma2(q1r, k01.x, s2[1][0]); s2[1][1] = fma2(q1r, k01.y, s2[1][1]);
            s2[1][2] = fma2(q1r, k23.x, s2[1][2]); s2[1][3] = fma2(q1r, k23.y, s2[1][3]);
            s2[2][0] = fma2(q2r, k01.x, s2[2][0]); s2[2][1] = fma2(q2r, k01.y, s2[2][1]);
            s2[2][2] = fma2(q2r, k23.x, s2[2][2]); s2[2][3] = fma2(q2r, k23.y, s2[2][3]);
            s2[3][0] = fma2(q3r, k01.x, s2[3][0]); s2[3][1] = fma2(q3r, k01.y, s2[3][1]);
            s2[3][2] = fma2(q3r, k23.x, s2[3][2]); s2[3][3] = fma2(q3r, k23.y, s2[3][3]);
        }

        // ---- relu^2 + transpose store, fused per k-pair (no r2 buffer) ----
        #pragma unroll
        for (int p = 0; p < 4; p++) {
            float2 f0 = unpack2(s2[0][p]);
            float2 f1 = unpack2(s2[1][p]);
            float2 f2 = unpack2(s2[2][p]);
            float2 f3 = unpack2(s2[3][p]);
            float a0 = fmaxf(f0.x, 0.f), a1 = fmaxf(f1.x, 0.f);
            float a2 = fmaxf(f2.x, 0.f), a3 = fmaxf(f3.x, 0.f);
            float b0 = fmaxf(f0.y, 0.f), b1 = fmaxf(f1.y, 0.f);
            float b2 = fmaxf(f2.y, 0.f), b3 = fmaxf(f3.y, 0.f);
            *(float4*)(Pt + (kc + 2*p)     * QP + qr) = make_float4(a0*a0, a1*a1, a2*a2, a3*a3);
            *(float4*)(Pt + (kc + 2*p + 1) * QP + qr) = make_float4(b0*b0, b1*b1, b2*b2, b3*b3);
        }
        __syncthreads();

        // ---- GEMM2: O[4q x 8d] += sum_k Pt[k][q] * Vs[k][d] ----
        #pragma unroll 8
        for (int k = 0; k < BK; k++) {
            float4 pv = *(const float4*)(Pt + k * QP + qr);
            u64 p0 = pack2(pv.x, pv.x), p1 = pack2(pv.y, pv.y);
            u64 p2 = pack2(pv.z, pv.z), p3 = pack2(pv.w, pv.w);
            ulonglong2 v01 = *(const ulonglong2*)(Vs + k * HD + kc);
            ulonglong2 v23 = *(const ulonglong2*)(Vs + k * HD + kc + 4);
            o2[0][0] = fma2(p0, v01.x, o2[0][0]); o2[0][1] = fma2(p0, v01.y, o2[0][1]);
            o2[0][2] = fma2(p0, v23.x, o2[0][2]); o2[0][3] = fma2(p0, v23.y, o2[0][3]);
            o2[1][0] = fma2(p1, v01.x, o2[1][0]); o2[1][1] = fma2(p1, v01.y, o2[1][1]);
            o2[1][2] = fma2(p1, v23.x, o2[1][2]); o2[1][3] = fma2(p1, v23.y, o2[1][3]);
            o2[2][0] = fma2(p2, v01.x, o2[2][0]); o2[2][1] = fma2(p2, v01.y, o2[2][1]);
            o2[2][2] = fma2(p2, v23.x, o2[2][2]); o2[2][3] = fma2(p2, v23.y, o2[2][3]);
            o2[3][0] = fma2(p3, v01.x, o2[3][0]); o2[3][1] = fma2(p3, v01.y, o2[3][1]);
            o2[3][2] = fma2(p3, v23.x, o2[3][2]); o2[3][3] = fma2(p3, v23.y, o2[3][3]);
        }
    }

    // Epilogue -> g_attn[n][l][h*64 + d]
    const int n = nh >> 3, h = nh & 7;
    #pragma unroll
    for (int qi = 0; qi < 4; qi++) {
        float2 a = unpack2(o2[qi][0]);
        float2 b = unpack2(o2[qi][1]);
        float2 c = unpack2(o2[qi][2]);
        float2 d = unpack2(o2[qi][3]);
        float* op = g_attn + ((size_t)n * SL + q0 + qr + qi) * FEA + h * HD + kc;
        *(float4*)(op)     = make_float4(a.x, a.y, b.x, b.y);
        *(float4*)(op + 4) = make_float4(c.x, c.y, d.x, d.y);
    }
}

// ---------------------------------------------------------------------------
// Kernel 3: out = g_attn[8192,512] @ Wo[512,64] + bo   (unchanged)
// ---------------------------------------------------------------------------
__global__ void __launch_bounds__(256)
out_kernel(const float* __restrict__ Wo,
           const float* __restrict__ bo,
           float* __restrict__ out)
{
    __shared__ __align__(16) float xs[64][68];
    __shared__ __align__(16) float wsh[64][64];

    const int row0 = blockIdx.x * 64;
    const int tid  = threadIdx.x;
    const int ty   = tid >> 4, tx = tid & 15;
    const int r0   = ty * 4,  c0 = tx * 4;

    u64 acc[4][2];
    #pragma unroll
    for (int i = 0; i < 4; i++) { acc[i][0] = 0ull; acc[i][1] = 0ull; }

    for (int kcb = 0; kcb < FEA; kcb += 64) {
        __syncthreads();
        #pragma unroll
        for (int j = 0; j < 4; j++) {
            int f  = tid + j * 256;
            int r  = f >> 4;
            int k4 = (f & 15) * 4;
            float4 xv = *(const float4*)(g_attn + ((size_t)(row0 + r)) * FEA + kcb + k4);
            *(float4*)&xs[r][k4] = xv;
            float4 wv = *(const float4*)(Wo + (size_t)(kcb + r) * HD + k4);
            *(float4*)&wsh[r][k4] = wv;
        }
        __syncthreads();

        #pragma unroll 8
        for (int k = 0; k < 64; k++) {
            ulonglong2 wv = *(const ulonglong2*)&wsh[k][c0];
            #pragma unroll
            for (int i = 0; i < 4; i++) {
                float xv = xs[r0 + i][k];
                u64 x2 = pack2(xv, xv);
                acc[i][0] = fma2(x2, wv.x, acc[i][0]);
                acc[i][1] = fma2(x2, wv.y, acc[i][1]);
            }
        }
    }

    float4 bv = *(const float4*)(bo + c0);
    #pragma unroll
    for (int i = 0; i < 4; i++) {
        float2 a = unpack2(acc[i][0]);
        float2 b = unpack2(acc[i][1]);
        float4 o = make_float4(a.x + bv.x, a.y + bv.y, b.x + bv.z, b.y + bv.w);
        *(float4*)(out + (size_t)(row0 + r0 + i) * HD + c0) = o;
    }
}

// ---------------------------------------------------------------------------
// Entry point
// ---------------------------------------------------------------------------
extern "C" void kernel_launch(void* const* d_in, const int* in_sizes, int n_in,
                              void* d_out, int out_size)
{
    const float* query = (const float*)d_in[0];
    const float* Wv    = (const float*)d_in[1];
    const float* Wk    = (const float*)d_in[2];
    const float* Wq    = (const float*)d_in[3];
    const float* Wo    = (const float*)d_in[4];
    const float* bo    = (const float*)d_in[5];
    float* out = (float*)d_out;

    const int proj_smem = (64 * XP + 3 * 64 * 64) * 4;               // 82944 B
    const int attn_smem = (64 * QP + 64 * KP + 64 * QP + 64 * HD) * 4; // 101376 B
    cudaFuncSetAttribute(proj_kernel, cudaFuncAttributeMaxDynamicSharedMemorySize, proj_smem);
    cudaFuncSetAttribute(attn_kernel, cudaFuncAttributeMaxDynamicSharedMemorySize, attn_smem);

    proj_kernel<<<dim3(16, 32), 256, proj_smem>>>(query, Wq, Wk, Wv);
    attn_kernel<<<dim3(16, 32), 256, attn_smem>>>();
    out_kernel<<<128, 256>>>(Wo, bo, out);
}